// round 17
// baseline (speedup 1.0000x reference)
#include <cuda_runtime.h>
#include <cuda_fp16.h>
#include <cstdint>

// ---------------------------------------------------------------------------
// FFT mura metric, v8:
//  - separate finalize kernel again (fused atomic tail measured slower)
//  - fft512 issue-count reduction:
//      * shared twiddle tables (pitch-10 rows, conflict-free LDS.128),
//        replacing per-thread sincosf + serial cmul chains
//      * exchange-2 via shared memory with XOR swizzle 72*mp + 8*t + (i^t)
//        (verified conflict-free both phases), replacing 8x8 shuffle transpose
//  - rows: scalar gray loads (measured best), packed real-pair FFTs,
//    Hermitian half-spectrum k<=256 stored fp16 (17 MB scratch)
//  - cols: direct scalar __ldcs scratch loads, interior k weighted x2
// ---------------------------------------------------------------------------

#define NTHR      256
#define REG_PITCH 580     // float2 per FFT-group region (>= 576)

__device__ __half2 g_scratch[32u * 257u * 512u];   // [b][k=0..256][r]
__device__ float   g_plow[32 * 65];
__device__ float   g_ptot[32 * 65];

struct alignas(8) H2X2 { __half2 e, o; };

__device__ __forceinline__ float2 cadd(float2 a, float2 b){ return make_float2(a.x+b.x, a.y+b.y); }
__device__ __forceinline__ float2 csub(float2 a, float2 b){ return make_float2(a.x-b.x, a.y-b.y); }
__device__ __forceinline__ float2 cmul(float2 a, float2 b){
    return make_float2(a.x*b.x - a.y*b.y, a.x*b.y + a.y*b.x);
}
__device__ __forceinline__ float2 mnegi(float2 a){ return make_float2( a.y, -a.x); } // * (-i)
__device__ __forceinline__ float2 mposi(float2 a){ return make_float2(-a.y,  a.x); } // * (+i)

__device__ __forceinline__ float fsqrt_approx(float x){
    float r; asm("sqrt.approx.f32 %0, %1;" : "=f"(r) : "f"(x)); return r;
}

// 8-point DFT, natural order: v[m'] = sum_m v_in[m] * w8^(m*m'), w8 = e^{-i pi/4}
__device__ __forceinline__ void dft8(float2* v){
    const float C = 0.70710678118654752440f;
    float2 t0 = cadd(v[0], v[4]);
    float2 t1 = csub(v[0], v[4]);
    float2 t2 = cadd(v[2], v[6]);
    float2 t3 = csub(v[2], v[6]);
    float2 E0 = cadd(t0, t2), E2 = csub(t0, t2);
    float2 E1 = cadd(t1, mnegi(t3));
    float2 E3 = cadd(t1, mposi(t3));
    float2 s0 = cadd(v[1], v[5]);
    float2 s1 = csub(v[1], v[5]);
    float2 s2 = cadd(v[3], v[7]);
    float2 s3 = csub(v[3], v[7]);
    float2 O0 = cadd(s0, s2), O2 = csub(s0, s2);
    float2 O1 = cadd(s1, mnegi(s3));
    float2 O3 = cadd(s1, mposi(s3));
    float2 w1O1 = make_float2(C*(O1.x + O1.y), C*(O1.y - O1.x));
    float2 w2O2 = mnegi(O2);
    float2 w3O3 = make_float2(C*(O3.y - O3.x), -C*(O3.x + O3.y));
    v[0] = cadd(E0, O0);   v[4] = csub(E0, O0);
    v[1] = cadd(E1, w1O1); v[5] = csub(E1, w1O1);
    v[2] = cadd(E2, w2O2); v[6] = csub(E2, w2O2);
    v[3] = cadd(E3, w3O3); v[7] = csub(E3, w3O3);
}

// Build twiddle tables: tw1[n][m] = e^{-2pi i n m/512} (n<64, m<8, pitch 10),
// tw2[i][t] = e^{-2pi i i t/64} (i<8, t<8, pitch 10). Caller syncs after.
__device__ __forceinline__ void build_tw(float2* stw1, float2* stw2, int tid){
    #pragma unroll
    for (int it = 0; it < 2; it++){
        int idx = tid + it * NTHR;          // 0..511
        int nn = idx >> 3, mm = idx & 7;
        float s, c;
        __sincosf((-6.28318530717958647693f / 512.0f) * (float)(nn * mm), &s, &c);
        stw1[nn * 10 + mm] = make_float2(c, s);
    }
    if (tid < 64){
        int ii = tid >> 3, tt = tid & 7;
        float s, c;
        __sincosf((-6.28318530717958647693f / 64.0f) * (float)(ii * tt), &s, &c);
        stw2[ii * 10 + tt] = make_float2(c, s);
    }
}

__device__ __forceinline__ void twiddle_apply(float2 a[8], const float2* row){
    const float4* tp = reinterpret_cast<const float4*>(row);
    float4 p0 = tp[0], p1 = tp[1], p2 = tp[2], p3 = tp[3];
    a[1] = cmul(a[1], make_float2(p0.z, p0.w));
    a[2] = cmul(a[2], make_float2(p1.x, p1.y));
    a[3] = cmul(a[3], make_float2(p1.z, p1.w));
    a[4] = cmul(a[4], make_float2(p2.x, p2.y));
    a[5] = cmul(a[5], make_float2(p2.z, p2.w));
    a[6] = cmul(a[6], make_float2(p3.x, p3.y));
    a[7] = cmul(a[7], make_float2(p3.z, p3.w));
}

// Cooperative 512-pt FFT by 64 threads (n = 0..63) sharing srow.
// Input : a[m] = x[n + 64*m]
// Output: a[t1] = X[(n>>3) + 8*(n&7) + 64*t1]
// Contains THREE __syncthreads(); all 256 block threads must call together.
// srow is "busy" until the caller syncs after return.
__device__ __forceinline__ void fft512(float2 a[8], float2* srow,
                                       const float2* stw1, const float2* stw2, int n){
    const int mp = n >> 3, i = n & 7;

    dft8(a);
    twiddle_apply(a, stw1 + n * 10);
    #pragma unroll
    for (int m = 0; m < 8; m++) srow[m * 72 + n] = a[m];
    __syncthreads();
    #pragma unroll
    for (int s = 0; s < 8; s++) a[s] = srow[mp * 72 + i + 8 * s];
    __syncthreads();                    // ex1 reads complete before ex2 writes

    dft8(a);
    twiddle_apply(a, stw2 + i * 10);
    // exchange-2: XOR-swizzled shared transpose within each 8-lane group
    #pragma unroll
    for (int t = 0; t < 8; t++) srow[mp * 72 + 8 * t + (i ^ t)] = a[t];
    __syncthreads();
    #pragma unroll
    for (int t = 0; t < 8; t++) a[t] = srow[mp * 72 + 8 * i + (t ^ i)];
    dft8(a);
}

// Kernel 1: gray + packed row-pair FFT + Hermitian unpack + fp16 transposed store
// Grid: 32 images * 64 row-groups; each block: 4 row-pairs (8 rows).
__global__ void __launch_bounds__(NTHR) fft_rows_kernel(const float* __restrict__ img){
    __shared__ float2 sbuf[4 * REG_PITCH];
    __shared__ alignas(16) float2 stw1[640];
    __shared__ alignas(16) float2 stw2[80];
    const int tid = threadIdx.x;
    const int b   = blockIdx.x >> 6;
    const int g   = blockIdx.x & 63;      // row group: rows g*8 .. g*8+7
    const int rr  = tid >> 6;             // pair index 0..3
    const int n   = tid & 63;

    const int row_e = g * 8 + rr * 2;
    const float* pe = img + (size_t)b * 786432u + (size_t)row_e * 512u;
    const float* po = pe + 512;

    float2 a[8];
    #pragma unroll
    for (int m = 0; m < 8; m++){
        int c = n + 64 * m;
        float ge = (pe[c] + pe[262144 + c] + pe[524288 + c]) * (1.0f / 3.0f);
        float go = (po[c] + po[262144 + c] + po[524288 + c]) * (1.0f / 3.0f);
        a[m] = make_float2(ge, go);       // z = even + i*odd
    }

    build_tw(stw1, stw2, tid);
    __syncthreads();

    float2* srow = sbuf + rr * REG_PITCH;
    fft512(a, srow, stw1, stw2, n);
    __syncthreads();                       // fft smem reads done before restage

    // stage Z in natural k order, pad every 8 to stagger banks
    {
        const int kb = (n >> 3) + 8 * (n & 7);
        #pragma unroll
        for (int t1 = 0; t1 < 8; t1++){
            int k = kb + 64 * t1;
            srow[k + (k >> 3)] = a[t1];
        }
    }
    __syncthreads();

    // Hermitian unpack: lane = 4*kk + p ; each lane emits (Xe,Xo) for (k, pair p)
    const int w  = tid >> 5, l = tid & 31;
    const int kk = l >> 2,  p = l & 3;
    const float2* shp = sbuf + p * REG_PITCH;
    #pragma unroll
    for (int it = 0; it < 5; it++){
        int  k   = it * 64 + w * 8 + kk;
        bool act = true;
        if (it == 4){ k = 256; act = (w == 0 && kk == 0); }
        if (act){
            int km = (512 - k) & 511;
            float2 zk = shp[k  + (k  >> 3)];
            float2 zm = shp[km + (km >> 3)];
            float2 Xe = make_float2(0.5f * (zk.x + zm.x), 0.5f * (zk.y - zm.y));
            float2 Xo = make_float2(0.5f * (zk.y + zm.y), 0.5f * (zm.x - zk.x));
            size_t off = ((size_t)(b * 257 + k) << 9) + (size_t)(g * 8 + 2 * p);
            H2X2 val;
            val.e = __float22half2_rn(Xe);
            val.o = __float22half2_rn(Xo);
            *reinterpret_cast<H2X2*>(&g_scratch[off]) = val;
        }
    }
}

// Kernel 2: column FFT for k = 0..256, masked magnitude sums (interior k x2)
__global__ void __launch_bounds__(NTHR) fft_cols_kernel(void){
    __shared__ float2 sbuf[4 * REG_PITCH];
    __shared__ alignas(16) float2 stw1[640];
    __shared__ alignas(16) float2 stw2[80];
    __shared__ float redL[8], redT[8];
    const int tid = threadIdx.x;
    const int b   = blockIdx.x / 65;
    const int kg  = blockIdx.x % 65;
    const int rr  = tid >> 6;
    const int n   = tid & 63;
    const int krow  = kg * 4 + rr;
    const bool valid = (krow < 257);

    const __half2* src = g_scratch + ((size_t)(b * 257 + (valid ? krow : 0)) << 9);
    float2 a[8];
    #pragma unroll
    for (int m = 0; m < 8; m++){
        __half2 h = __ldcs(src + n + 64 * m);
        float2 v = __half22float2(h);
        a[m] = valid ? v : make_float2(0.0f, 0.0f);
    }

    build_tw(stw1, stw2, tid);
    __syncthreads();

    fft512(a, sbuf + rr * REG_PITCH, stw1, stw2, n);

    // a[t1] = F[u][krow], u = (n>>3) + 8*(n&7) + 64*t1
    const int ub = (n >> 3) + 8 * (n & 7);
    float wgt = !valid ? 0.0f : ((krow == 0 || krow == 256) ? 1.0f : 2.0f);
    float dx  = (float)(krow - 256);
    float dx2 = dx * dx;
    float L = 0.0f, T = 0.0f;
    #pragma unroll
    for (int t1 = 0; t1 < 8; t1++){
        int u = ub + 64 * t1;
        float2 v = a[t1];
        float mag = fsqrt_approx(v.x * v.x + v.y * v.y);
        T += mag;
        float dy = (float)(u - 256);
        if (dy * dy + dx2 <= 2621.44f) L += mag;   // (512*0.1)^2
    }
    L *= wgt; T *= wgt;

    #pragma unroll
    for (int o = 16; o; o >>= 1){
        L += __shfl_down_sync(0xffffffffu, L, o);
        T += __shfl_down_sync(0xffffffffu, T, o);
    }
    const int wid = tid >> 5, lane = tid & 31;
    if (lane == 0){ redL[wid] = L; redT[wid] = T; }
    __syncthreads();
    if (tid == 0){
        float sl = 0.0f, st = 0.0f;
        #pragma unroll
        for (int q = 0; q < 8; q++){ sl += redL[q]; st += redT[q]; }
        g_plow[blockIdx.x] = sl;
        g_ptot[blockIdx.x] = st;
    }
}

// Kernel 3: deterministic final reduction -> scalar
__global__ void __launch_bounds__(1024) finalize_kernel(float* __restrict__ out){
    const int t = threadIdx.x;
    const int b = t >> 5, lane = t & 31;
    float L = 0.0f, T = 0.0f;
    for (int i = lane; i < 65; i += 32){
        L += g_plow[b * 65 + i];
        T += g_ptot[b * 65 + i];
    }
    #pragma unroll
    for (int o = 16; o; o >>= 1){
        L += __shfl_down_sync(0xffffffffu, L, o);
        T += __shfl_down_sync(0xffffffffu, T, o);
    }
    __shared__ float s[32];
    if (lane == 0) s[b] = L / T;
    __syncthreads();
    if (t < 32){
        float v = s[t];
        #pragma unroll
        for (int o = 16; o; o >>= 1) v += __shfl_down_sync(0xffffffffu, v, o);
        if (t == 0) out[0] = v * (1.0f / 32.0f);
    }
}

extern "C" void kernel_launch(void* const* d_in, const int* in_sizes, int n_in,
                              void* d_out, int out_size){
    const float* img = (const float*)d_in[0];
    float* out = (float*)d_out;
    (void)in_sizes; (void)n_in; (void)out_size;

    fft_rows_kernel<<<32 * 64, NTHR>>>(img);
    fft_cols_kernel<<<32 * 65, NTHR>>>();
    finalize_kernel<<<1, 1024>>>(out);
}